// round 1
// baseline (speedup 1.0000x reference)
#include <cuda_runtime.h>
#include <math.h>

#define NB 16
#define TDIM 1024
#define DEMB 1024

// Scratch: __device__ globals (allocation-free rule)
__device__ float g_Q[(size_t)NB * TDIM * DEMB];
__device__ float g_K[(size_t)NB * TDIM * DEMB];
__device__ float g_V[(size_t)NB * TDIM * DEMB];
__device__ float g_S[(size_t)NB * TDIM * TDIM];

constexpr int BM = 128, BN = 128, BK = 8, TM = 8, TN = 8;

// C[m,n] = alpha * sum_k A[m,k] * B[n,k]  (+ bias[n])      (NT gemm)
// batched via blockIdx.z with strides; causalSkip drops blocks fully above diagonal
__global__ __launch_bounds__(256) void gemm_nt(
    const float* __restrict__ A, const float* __restrict__ B,
    const float* __restrict__ bias, float* __restrict__ C,
    int M, int N, int K, float alpha,
    long strideA, long strideB, long strideC, int causalSkip)
{
    int bx = blockIdx.x, by = blockIdx.y, bz = blockIdx.z;
    if (causalSkip && bx > by) return;   // BM==BN: whole block masked
    A += (size_t)bz * strideA;
    B += (size_t)bz * strideB;
    C += (size_t)bz * strideC;

    __shared__ float As[BK][BM];
    __shared__ float Bs[BK][BN];

    int tid = threadIdx.x;
    int tr = tid >> 4, tc = tid & 15;         // 16x16 threads of 8x8
    int lr = tid >> 1, lc = (tid & 1) * 4;    // loader: 128 rows x 8 cols via float4

    const float* Ap = A + (size_t)(by * BM + lr) * K + lc;
    const float* Bp = B + (size_t)(bx * BN + lr) * K + lc;

    float acc[TM][TN];
#pragma unroll
    for (int i = 0; i < TM; i++)
#pragma unroll
        for (int j = 0; j < TN; j++) acc[i][j] = 0.f;

    for (int k0 = 0; k0 < K; k0 += BK) {
        float4 av = *(const float4*)(Ap + k0);
        float4 bv = *(const float4*)(Bp + k0);
        As[lc + 0][lr] = av.x; As[lc + 1][lr] = av.y;
        As[lc + 2][lr] = av.z; As[lc + 3][lr] = av.w;
        Bs[lc + 0][lr] = bv.x; Bs[lc + 1][lr] = bv.y;
        Bs[lc + 2][lr] = bv.z; Bs[lc + 3][lr] = bv.w;
        __syncthreads();
#pragma unroll
        for (int kk = 0; kk < BK; kk++) {
            float ra[TM], rb[TN];
#pragma unroll
            for (int i = 0; i < TM; i++) ra[i] = As[kk][tr * TM + i];
#pragma unroll
            for (int j = 0; j < TN; j++) rb[j] = Bs[kk][tc * TN + j];
#pragma unroll
            for (int i = 0; i < TM; i++)
#pragma unroll
                for (int j = 0; j < TN; j++)
                    acc[i][j] += ra[i] * rb[j];
        }
        __syncthreads();
    }

    int cn = bx * BN + tc * TN;
#pragma unroll
    for (int i = 0; i < TM; i++) {
        int cm = by * BM + tr * TM + i;
        float* crow = C + (size_t)cm * N + cn;
#pragma unroll
        for (int j = 0; j < TN; j++) {
            float v = acc[i][j] * alpha;
            if (bias) v += bias[cn + j];
            crow[j] = v;
        }
    }
}

// C[m,n] = sum_k A[m,k] * B[k,n]      (NN gemm, batched)
// causalK clips k-loop at (by+1)*BM (entries beyond are zero in P)
__global__ __launch_bounds__(256) void gemm_nn(
    const float* __restrict__ A, const float* __restrict__ B,
    float* __restrict__ C,
    int M, int N, int K,
    long strideA, long strideB, long strideC, int causalK)
{
    int bx = blockIdx.x, by = blockIdx.y, bz = blockIdx.z;
    A += (size_t)bz * strideA;
    B += (size_t)bz * strideB;
    C += (size_t)bz * strideC;

    __shared__ float As[BK][BM];
    __shared__ float Bs[BK][BN];

    int tid = threadIdx.x;
    int tr = tid >> 4, tc = tid & 15;
    int lrA = tid >> 1, lcA = (tid & 1) * 4;   // A loader (transpose into As)
    int lrB = tid >> 5, lcB = (tid & 31) * 4;  // B loader (direct rows)

    const float* Ap = A + (size_t)(by * BM + lrA) * K + lcA;

    int kEnd = causalK ? min(K, (by + 1) * BM) : K;

    float acc[TM][TN];
#pragma unroll
    for (int i = 0; i < TM; i++)
#pragma unroll
        for (int j = 0; j < TN; j++) acc[i][j] = 0.f;

    for (int k0 = 0; k0 < kEnd; k0 += BK) {
        float4 av = *(const float4*)(Ap + k0);
        float4 bv = *(const float4*)(B + (size_t)(k0 + lrB) * N + bx * BN + lcB);
        As[lcA + 0][lrA] = av.x; As[lcA + 1][lrA] = av.y;
        As[lcA + 2][lrA] = av.z; As[lcA + 3][lrA] = av.w;
        *(float4*)&Bs[lrB][lcB] = bv;
        __syncthreads();
#pragma unroll
        for (int kk = 0; kk < BK; kk++) {
            float ra[TM], rb[TN];
#pragma unroll
            for (int i = 0; i < TM; i++) ra[i] = As[kk][tr * TM + i];
#pragma unroll
            for (int j = 0; j < TN; j++) rb[j] = Bs[kk][tc * TN + j];
#pragma unroll
            for (int i = 0; i < TM; i++)
#pragma unroll
                for (int j = 0; j < TN; j++)
                    acc[i][j] += ra[i] * rb[j];
        }
        __syncthreads();
    }

    int cn = bx * BN + tc * TN;
#pragma unroll
    for (int i = 0; i < TM; i++) {
        int cm = by * BM + tr * TM + i;
        float* crow = C + (size_t)cm * N + cn;
#pragma unroll
        for (int j = 0; j < TN; j++) crow[j] = acc[i][j];
    }
}

// Causal row softmax in place on S[b,q,0..q]; zeros the tail [q+1, T)
__global__ void softmax_causal(float* __restrict__ S)
{
    int q = blockIdx.x, b = blockIdx.y;
    float* row = S + ((size_t)b * TDIM + q) * TDIM;
    int len = q + 1;
    int tid = threadIdx.x;
    int lane = tid & 31, warp = tid >> 5;

    __shared__ float smax[8];
    __shared__ float ssum[8];

    float m = -1e30f;
    for (int i = tid; i < len; i += 256) m = fmaxf(m, row[i]);
#pragma unroll
    for (int o = 16; o; o >>= 1) m = fmaxf(m, __shfl_xor_sync(0xffffffffu, m, o));
    if (lane == 0) smax[warp] = m;
    __syncthreads();
    if (tid == 0) {
        float v = smax[0];
#pragma unroll
        for (int i = 1; i < 8; i++) v = fmaxf(v, smax[i]);
        smax[0] = v;
    }
    __syncthreads();
    m = smax[0];

    float sum = 0.f;
    for (int i = tid; i < len; i += 256) {
        float e = __expf(row[i] - m);
        row[i] = e;
        sum += e;
    }
#pragma unroll
    for (int o = 16; o; o >>= 1) sum += __shfl_xor_sync(0xffffffffu, sum, o);
    if (lane == 0) ssum[warp] = sum;
    __syncthreads();
    if (tid == 0) {
        float v = 0.f;
#pragma unroll
        for (int i = 0; i < 8; i++) v += ssum[i];
        ssum[0] = v;
    }
    __syncthreads();
    float inv = 1.f / ssum[0];

    for (int i = tid; i < len; i += 256) row[i] *= inv;
    for (int i = len + tid; i < TDIM; i += 256) row[i] = 0.f;
}

extern "C" void kernel_launch(void* const* d_in, const int* in_sizes, int n_in,
                              void* d_out, int out_size)
{
    const float* qx = (const float*)d_in[0];
    const float* kx = (const float*)d_in[1];
    const float* vx = (const float*)d_in[2];
    const float* Wq = (const float*)d_in[3];
    const float* bq = (const float*)d_in[4];
    const float* Wk = (const float*)d_in[5];
    const float* bk = (const float*)d_in[6];
    const float* Wv = (const float*)d_in[7];
    const float* bv = (const float*)d_in[8];
    float* out = (float*)d_out;

    float *pQ, *pK, *pV, *pS;
    cudaGetSymbolAddress((void**)&pQ, g_Q);
    cudaGetSymbolAddress((void**)&pK, g_K);
    cudaGetSymbolAddress((void**)&pV, g_V);
    cudaGetSymbolAddress((void**)&pS, g_S);

    dim3 blk(256);

    // Projections: X(16384x1024) @ W^T + b  -> Q/K/V scratch
    dim3 gproj(DEMB / BN, (NB * TDIM) / BM, 1);
    gemm_nt<<<gproj, blk>>>(qx, Wq, bq, pQ, NB * TDIM, DEMB, DEMB, 1.f, 0, 0, 0, 0);
    gemm_nt<<<gproj, blk>>>(kx, Wk, bk, pK, NB * TDIM, DEMB, DEMB, 1.f, 0, 0, 0, 0);
    gemm_nt<<<gproj, blk>>>(vx, Wv, bv, pV, NB * TDIM, DEMB, DEMB, 1.f, 0, 0, 0, 0);

    // S = Q K^T / 32, batched over 16, upper-triangle blocks skipped
    dim3 gattn(TDIM / BN, TDIM / BM, NB);
    gemm_nt<<<gattn, blk>>>(pQ, pK, nullptr, pS, TDIM, TDIM, DEMB, 0.03125f,
                            (long)TDIM * DEMB, (long)TDIM * DEMB,
                            (long)TDIM * TDIM, 1);

    // causal softmax in place (writes exact zeros above diagonal)
    softmax_causal<<<dim3(TDIM, NB), 256>>>(pS);

    // O = P V, k-loop clipped at the diagonal
    gemm_nn<<<gattn, blk>>>(pS, pV, out, TDIM, DEMB, TDIM,
                            (long)TDIM * TDIM, (long)TDIM * DEMB,
                            (long)TDIM * DEMB, 1);
}

// round 2
// speedup vs baseline: 3.1405x; 3.1405x over previous
#include <cuda_runtime.h>
#include <math.h>

#define NB 16
#define TDIM 1024
#define DEMB 1024

// Scratch: __device__ globals (allocation-free rule)
__device__ float g_Q[(size_t)NB * TDIM * DEMB];
__device__ float g_K[(size_t)NB * TDIM * DEMB];
__device__ float g_V[(size_t)NB * TDIM * DEMB];
__device__ float g_S[(size_t)NB * TDIM * TDIM];

constexpr int BM = 128, BN = 128, BK = 16;
constexpr int SST = 20;  // smem row stride (floats): conflict-free for frag pattern

__device__ __forceinline__ unsigned f2tf(float x) {
    unsigned r;
    asm("cvt.rna.tf32.f32 %0, %1;" : "=r"(r) : "f"(x));
    return r;
}

__device__ __forceinline__ void mma8(float* c, const unsigned* a, const unsigned* b) {
    asm volatile(
        "mma.sync.aligned.m16n8k8.row.col.f32.tf32.tf32.f32 "
        "{%0,%1,%2,%3},{%4,%5,%6,%7},{%8,%9},{%0,%1,%2,%3};"
        : "+f"(c[0]), "+f"(c[1]), "+f"(c[2]), "+f"(c[3])
        : "r"(a[0]), "r"(a[1]), "r"(a[2]), "r"(a[3]), "r"(b[0]), "r"(b[1]));
}

// ---------------------------------------------------------------------------
// NT gemm: C[m,n] = alpha * sum_k A[m,k]*B[n,k] (+bias[n]); batched (bz)
// causalSkip: drop blocks with bx > by (BM==BN)
// ---------------------------------------------------------------------------
__global__ __launch_bounds__(256, 2) void gemm_nt_tf32(
    const float* __restrict__ A, const float* __restrict__ B,
    const float* __restrict__ bias, float* __restrict__ C,
    int M, int N, int K, float alpha,
    long strideA, long strideB, long strideC, int causalSkip)
{
    int bx = blockIdx.x, by = blockIdx.y, bz = blockIdx.z;
    if (causalSkip && bx > by) return;
    A += (size_t)bz * strideA;
    B += (size_t)bz * strideB;
    C += (size_t)bz * strideC;

    __shared__ unsigned sA[2][BM * SST];
    __shared__ unsigned sB[2][BN * SST];

    int tid = threadIdx.x;
    int warp = tid >> 5, lane = tid & 31;
    int wr = warp & 3, wc = warp >> 2;       // 4x2 warp grid; warp tile 32x64
    int qr = lane >> 2, rr = lane & 3;

    int lr = tid >> 2;                        // 0..63
    int lc4 = (tid & 3) * 4;                  // k offset 0,4,8,12

    const float* Ap = A + (size_t)(by * BM + lr) * K + lc4;
    const float* Bp = B + (size_t)(bx * BN + lr) * K + lc4;

    float acc[2][8][4];
#pragma unroll
    for (int mt = 0; mt < 2; mt++)
#pragma unroll
        for (int nt = 0; nt < 8; nt++)
#pragma unroll
            for (int i = 0; i < 4; i++) acc[mt][nt][i] = 0.f;

    float4 ra0, ra1, rb0, rb1;
    int nIter = K / BK;

    // prologue: tile 0
    ra0 = *(const float4*)(Ap);
    ra1 = *(const float4*)(Ap + (size_t)64 * K);
    rb0 = *(const float4*)(Bp);
    rb1 = *(const float4*)(Bp + (size_t)64 * K);
    {
        uint4 u;
        u.x = f2tf(ra0.x); u.y = f2tf(ra0.y); u.z = f2tf(ra0.z); u.w = f2tf(ra0.w);
        *(uint4*)&sA[0][lr * SST + lc4] = u;
        u.x = f2tf(ra1.x); u.y = f2tf(ra1.y); u.z = f2tf(ra1.z); u.w = f2tf(ra1.w);
        *(uint4*)&sA[0][(lr + 64) * SST + lc4] = u;
        u.x = f2tf(rb0.x); u.y = f2tf(rb0.y); u.z = f2tf(rb0.z); u.w = f2tf(rb0.w);
        *(uint4*)&sB[0][lr * SST + lc4] = u;
        u.x = f2tf(rb1.x); u.y = f2tf(rb1.y); u.z = f2tf(rb1.z); u.w = f2tf(rb1.w);
        *(uint4*)&sB[0][(lr + 64) * SST + lc4] = u;
    }
    __syncthreads();

    for (int it = 0; it < nIter; ++it) {
        int buf = it & 1;
        if (it + 1 < nIter) {
            int k0 = (it + 1) * BK;
            ra0 = *(const float4*)(Ap + k0);
            ra1 = *(const float4*)(Ap + (size_t)64 * K + k0);
            rb0 = *(const float4*)(Bp + k0);
            rb1 = *(const float4*)(Bp + (size_t)64 * K + k0);
        }
#pragma unroll
        for (int ks = 0; ks < 2; ks++) {
            int kb = ks * 8;
            unsigned af[2][4], bf[8][2];
#pragma unroll
            for (int mt = 0; mt < 2; mt++) {
                int m = wr * 32 + mt * 16 + qr;
                af[mt][0] = sA[buf][m * SST + kb + rr];
                af[mt][1] = sA[buf][(m + 8) * SST + kb + rr];
                af[mt][2] = sA[buf][m * SST + kb + rr + 4];
                af[mt][3] = sA[buf][(m + 8) * SST + kb + rr + 4];
            }
#pragma unroll
            for (int nt = 0; nt < 8; nt++) {
                int n = wc * 64 + nt * 8 + qr;
                bf[nt][0] = sB[buf][n * SST + kb + rr];
                bf[nt][1] = sB[buf][n * SST + kb + rr + 4];
            }
#pragma unroll
            for (int mt = 0; mt < 2; mt++)
#pragma unroll
                for (int nt = 0; nt < 8; nt++)
                    mma8(acc[mt][nt], af[mt], bf[nt]);
        }
        if (it + 1 < nIter) {
            int nb = buf ^ 1;
            uint4 u;
            u.x = f2tf(ra0.x); u.y = f2tf(ra0.y); u.z = f2tf(ra0.z); u.w = f2tf(ra0.w);
            *(uint4*)&sA[nb][lr * SST + lc4] = u;
            u.x = f2tf(ra1.x); u.y = f2tf(ra1.y); u.z = f2tf(ra1.z); u.w = f2tf(ra1.w);
            *(uint4*)&sA[nb][(lr + 64) * SST + lc4] = u;
            u.x = f2tf(rb0.x); u.y = f2tf(rb0.y); u.z = f2tf(rb0.z); u.w = f2tf(rb0.w);
            *(uint4*)&sB[nb][lr * SST + lc4] = u;
            u.x = f2tf(rb1.x); u.y = f2tf(rb1.y); u.z = f2tf(rb1.z); u.w = f2tf(rb1.w);
            *(uint4*)&sB[nb][(lr + 64) * SST + lc4] = u;
        }
        __syncthreads();
    }

    // epilogue
#pragma unroll
    for (int mt = 0; mt < 2; mt++) {
#pragma unroll
        for (int nt = 0; nt < 8; nt++) {
            int row = by * BM + wr * 32 + mt * 16 + qr;
            int col = bx * BN + wc * 64 + nt * 8 + rr * 2;
            float b0 = bias ? bias[col] : 0.f;
            float b1 = bias ? bias[col + 1] : 0.f;
            float2 v;
            v.x = acc[mt][nt][0] * alpha + b0;
            v.y = acc[mt][nt][1] * alpha + b1;
            *(float2*)&C[(size_t)row * N + col] = v;
            v.x = acc[mt][nt][2] * alpha + b0;
            v.y = acc[mt][nt][3] * alpha + b1;
            *(float2*)&C[(size_t)(row + 8) * N + col] = v;
        }
    }
}

// ---------------------------------------------------------------------------
// NN gemm: C[m,n] = sum_k A[m,k]*B[k,n]; batched (bz)
// causalK: clip k loop at (by+1)*BM
// ---------------------------------------------------------------------------
__global__ __launch_bounds__(256, 2) void gemm_nn_tf32(
    const float* __restrict__ A, const float* __restrict__ B,
    float* __restrict__ C,
    int M, int N, int K,
    long strideA, long strideB, long strideC, int causalK)
{
    int bx = blockIdx.x, by = blockIdx.y, bz = blockIdx.z;
    A += (size_t)bz * strideA;
    B += (size_t)bz * strideB;
    C += (size_t)bz * strideC;

    __shared__ unsigned sA[2][BM * SST];
    __shared__ unsigned sB[2][BN * SST];

    int tid = threadIdx.x;
    int warp = tid >> 5, lane = tid & 31;
    int wr = warp & 3, wc = warp >> 2;
    int qr = lane >> 2, rr = lane & 3;

    int lr = tid >> 2;
    int lc4 = (tid & 3) * 4;
    // B (k-major transpose) loader: thread handles n = tid&127, k group kg
    int bn = tid & 127;
    int kg = tid >> 7;  // 0 or 1 -> k offsets {kg*4..kg*4+3, 8+kg*4..}

    const float* Ap = A + (size_t)(by * BM + lr) * K + lc4;
    const float* Bp = B + (size_t)(bx * BN + bn);

    int kEnd = causalK ? min(K, (by + 1) * BM) : K;
    int nIter = kEnd / BK;

    float acc[2][8][4];
#pragma unroll
    for (int mt = 0; mt < 2; mt++)
#pragma unroll
        for (int nt = 0; nt < 8; nt++)
#pragma unroll
            for (int i = 0; i < 4; i++) acc[mt][nt][i] = 0.f;

    float4 ra0, ra1;
    float rb[8];

    // prologue tile 0
    ra0 = *(const float4*)(Ap);
    ra1 = *(const float4*)(Ap + (size_t)64 * K);
#pragma unroll
    for (int r = 0; r < 4; r++) {
        rb[r]     = Bp[(size_t)(kg * 4 + r) * N];
        rb[4 + r] = Bp[(size_t)(8 + kg * 4 + r) * N];
    }
    {
        uint4 u;
        u.x = f2tf(ra0.x); u.y = f2tf(ra0.y); u.z = f2tf(ra0.z); u.w = f2tf(ra0.w);
        *(uint4*)&sA[0][lr * SST + lc4] = u;
        u.x = f2tf(ra1.x); u.y = f2tf(ra1.y); u.z = f2tf(ra1.z); u.w = f2tf(ra1.w);
        *(uint4*)&sA[0][(lr + 64) * SST + lc4] = u;
        u.x = f2tf(rb[0]); u.y = f2tf(rb[1]); u.z = f2tf(rb[2]); u.w = f2tf(rb[3]);
        *(uint4*)&sB[0][bn * SST + kg * 4] = u;
        u.x = f2tf(rb[4]); u.y = f2tf(rb[5]); u.z = f2tf(rb[6]); u.w = f2tf(rb[7]);
        *(uint4*)&sB[0][bn * SST + 8 + kg * 4] = u;
    }
    __syncthreads();

    for (int it = 0; it < nIter; ++it) {
        int buf = it & 1;
        if (it + 1 < nIter) {
            int k0 = (it + 1) * BK;
            ra0 = *(const float4*)(Ap + k0);
            ra1 = *(const float4*)(Ap + (size_t)64 * K + k0);
#pragma unroll
            for (int r = 0; r < 4; r++) {
                rb[r]     = Bp[(size_t)(k0 + kg * 4 + r) * N];
                rb[4 + r] = Bp[(size_t)(k0 + 8 + kg * 4 + r) * N];
            }
        }
#pragma unroll
        for (int ks = 0; ks < 2; ks++) {
            int kb = ks * 8;
            unsigned af[2][4], bf[8][2];
#pragma unroll
            for (int mt = 0; mt < 2; mt++) {
                int m = wr * 32 + mt * 16 + qr;
                af[mt][0] = sA[buf][m * SST + kb + rr];
                af[mt][1] = sA[buf][(m + 8) * SST + kb + rr];
                af[mt][2] = sA[buf][m * SST + kb + rr + 4];
                af[mt][3] = sA[buf][(m + 8) * SST + kb + rr + 4];
            }
#pragma unroll
            for (int nt = 0; nt < 8; nt++) {
                int n = wc * 64 + nt * 8 + qr;
                bf[nt][0] = sB[buf][n * SST + kb + rr];
                bf[nt][1] = sB[buf][n * SST + kb + rr + 4];
            }
#pragma unroll
            for (int mt = 0; mt < 2; mt++)
#pragma unroll
                for (int nt = 0; nt < 8; nt++)
                    mma8(acc[mt][nt], af[mt], bf[nt]);
        }
        if (it + 1 < nIter) {
            int nb = buf ^ 1;
            uint4 u;
            u.x = f2tf(ra0.x); u.y = f2tf(ra0.y); u.z = f2tf(ra0.z); u.w = f2tf(ra0.w);
            *(uint4*)&sA[nb][lr * SST + lc4] = u;
            u.x = f2tf(ra1.x); u.y = f2tf(ra1.y); u.z = f2tf(ra1.z); u.w = f2tf(ra1.w);
            *(uint4*)&sA[nb][(lr + 64) * SST + lc4] = u;
            u.x = f2tf(rb[0]); u.y = f2tf(rb[1]); u.z = f2tf(rb[2]); u.w = f2tf(rb[3]);
            *(uint4*)&sB[nb][bn * SST + kg * 4] = u;
            u.x = f2tf(rb[4]); u.y = f2tf(rb[5]); u.z = f2tf(rb[6]); u.w = f2tf(rb[7]);
            *(uint4*)&sB[nb][bn * SST + 8 + kg * 4] = u;
        }
        __syncthreads();
    }

#pragma unroll
    for (int mt = 0; mt < 2; mt++) {
#pragma unroll
        for (int nt = 0; nt < 8; nt++) {
            int row = by * BM + wr * 32 + mt * 16 + qr;
            int col = bx * BN + wc * 64 + nt * 8 + rr * 2;
            float2 v;
            v.x = acc[mt][nt][0]; v.y = acc[mt][nt][1];
            *(float2*)&C[(size_t)row * N + col] = v;
            v.x = acc[mt][nt][2]; v.y = acc[mt][nt][3];
            *(float2*)&C[(size_t)(row + 8) * N + col] = v;
        }
    }
}

// ---------------------------------------------------------------------------
// Causal row softmax in place on S[b,q,0..q]; zeros the tail [q+1, T)
// ---------------------------------------------------------------------------
__global__ void softmax_causal(float* __restrict__ S)
{
    int q = blockIdx.x, b = blockIdx.y;
    float* row = S + ((size_t)b * TDIM + q) * TDIM;
    int len = q + 1;
    int tid = threadIdx.x;
    int lane = tid & 31, warp = tid >> 5;

    __shared__ float smax[8];
    __shared__ float ssum[8];

    float m = -1e30f;
    for (int i = tid; i < len; i += 256) m = fmaxf(m, row[i]);
#pragma unroll
    for (int o = 16; o; o >>= 1) m = fmaxf(m, __shfl_xor_sync(0xffffffffu, m, o));
    if (lane == 0) smax[warp] = m;
    __syncthreads();
    if (tid == 0) {
        float v = smax[0];
#pragma unroll
        for (int i = 1; i < 8; i++) v = fmaxf(v, smax[i]);
        smax[0] = v;
    }
    __syncthreads();
    m = smax[0];

    float sum = 0.f;
    for (int i = tid; i < len; i += 256) {
        float e = __expf(row[i] - m);
        row[i] = e;
        sum += e;
    }
#pragma unroll
    for (int o = 16; o; o >>= 1) sum += __shfl_xor_sync(0xffffffffu, sum, o);
    if (lane == 0) ssum[warp] = sum;
    __syncthreads();
    if (tid == 0) {
        float v = 0.f;
#pragma unroll
        for (int i = 0; i < 8; i++) v += ssum[i];
        ssum[0] = v;
    }
    __syncthreads();
    float inv = 1.f / ssum[0];

    for (int i = tid; i < len; i += 256) row[i] *= inv;
    for (int i = len + tid; i < TDIM; i += 256) row[i] = 0.f;
}

extern "C" void kernel_launch(void* const* d_in, const int* in_sizes, int n_in,
                              void* d_out, int out_size)
{
    const float* qx = (const float*)d_in[0];
    const float* kx = (const float*)d_in[1];
    const float* vx = (const float*)d_in[2];
    const float* Wq = (const float*)d_in[3];
    const float* bq = (const float*)d_in[4];
    const float* Wk = (const float*)d_in[5];
    const float* bk = (const float*)d_in[6];
    const float* Wv = (const float*)d_in[7];
    const float* bv = (const float*)d_in[8];
    float* out = (float*)d_out;

    float *pQ, *pK, *pV, *pS;
    cudaGetSymbolAddress((void**)&pQ, g_Q);
    cudaGetSymbolAddress((void**)&pK, g_K);
    cudaGetSymbolAddress((void**)&pV, g_V);
    cudaGetSymbolAddress((void**)&pS, g_S);

    dim3 blk(256);

    // Projections: X(16384x1024) @ W^T + b  -> Q/K/V scratch
    dim3 gproj(DEMB / BN, (NB * TDIM) / BM, 1);
    gemm_nt_tf32<<<gproj, blk>>>(qx, Wq, bq, pQ, NB * TDIM, DEMB, DEMB, 1.f, 0, 0, 0, 0);
    gemm_nt_tf32<<<gproj, blk>>>(kx, Wk, bk, pK, NB * TDIM, DEMB, DEMB, 1.f, 0, 0, 0, 0);
    gemm_nt_tf32<<<gproj, blk>>>(vx, Wv, bv, pV, NB * TDIM, DEMB, DEMB, 1.f, 0, 0, 0, 0);

    // S = Q K^T / 32, batched over 16, upper-triangle blocks skipped
    dim3 gattn(TDIM / BN, TDIM / BM, NB);
    gemm_nt_tf32<<<gattn, blk>>>(pQ, pK, nullptr, pS, TDIM, TDIM, DEMB, 0.03125f,
                                 (long)TDIM * DEMB, (long)TDIM * DEMB,
                                 (long)TDIM * TDIM, 1);

    // causal softmax in place (writes exact zeros above diagonal)
    softmax_causal<<<dim3(TDIM, NB), 256>>>(pS);

    // O = P V, k-loop clipped at the diagonal
    gemm_nn_tf32<<<gattn, blk>>>(pS, pV, out, TDIM, DEMB, TDIM,
                                 (long)TDIM * TDIM, (long)TDIM * DEMB,
                                 (long)TDIM * DEMB, 1);
}

// round 3
// speedup vs baseline: 4.1694x; 1.3277x over previous
#include <cuda_runtime.h>
#include <cuda_fp16.h>
#include <math.h>

#define NB 16
#define TDIM 1024
#define DEMB 1024

// Scratch (__device__ globals per allocation-free rule)
__device__ __half g_Q[(size_t)NB * TDIM * DEMB];
__device__ __half g_K[(size_t)NB * TDIM * DEMB];
__device__ __half g_V[(size_t)NB * TDIM * DEMB];
__device__ float  g_S[(size_t)NB * TDIM * TDIM];

constexpr int BM = 128, BN = 128, BK = 32;  // BK in halves
constexpr int SST = 40;                     // smem row stride in halves (80B): conflict-free

__device__ __forceinline__ unsigned packh2(float x, float y) {
    __half2 h = __floats2half2_rn(x, y);
    return *(unsigned*)&h;
}

__device__ __forceinline__ void ldsm4(unsigned& r0, unsigned& r1, unsigned& r2, unsigned& r3,
                                      unsigned saddr) {
    asm volatile("ldmatrix.sync.aligned.m8n8.x4.shared.b16 {%0,%1,%2,%3}, [%4];"
                 : "=r"(r0), "=r"(r1), "=r"(r2), "=r"(r3) : "r"(saddr));
}

__device__ __forceinline__ void mma16816(float* c, const unsigned* a, const unsigned* b) {
    asm volatile(
        "mma.sync.aligned.m16n8k16.row.col.f32.f16.f16.f32 "
        "{%0,%1,%2,%3},{%4,%5,%6,%7},{%8,%9},{%0,%1,%2,%3};"
        : "+f"(c[0]), "+f"(c[1]), "+f"(c[2]), "+f"(c[3])
        : "r"(a[0]), "r"(a[1]), "r"(a[2]), "r"(a[3]), "r"(b[0]), "r"(b[1]));
}

// load 16 contiguous k-elements from row-major source, as 16 halves in 2 uint4
template <typename T>
__device__ __forceinline__ void load16(const T* p, uint4& u0, uint4& u1);

template <>
__device__ __forceinline__ void load16<float>(const float* p, uint4& u0, uint4& u1) {
    float4 f0 = *(const float4*)(p);
    float4 f1 = *(const float4*)(p + 4);
    float4 f2 = *(const float4*)(p + 8);
    float4 f3 = *(const float4*)(p + 12);
    u0.x = packh2(f0.x, f0.y); u0.y = packh2(f0.z, f0.w);
    u0.z = packh2(f1.x, f1.y); u0.w = packh2(f1.z, f1.w);
    u1.x = packh2(f2.x, f2.y); u1.y = packh2(f2.z, f2.w);
    u1.z = packh2(f3.x, f3.y); u1.w = packh2(f3.z, f3.w);
}

template <>
__device__ __forceinline__ void load16<__half>(const __half* p, uint4& u0, uint4& u1) {
    u0 = *(const uint4*)(p);
    u1 = *(const uint4*)(p + 8);
}

// ---------------------------------------------------------------------------
// NT gemm: C[m,n] = alpha * sum_k A[m,k]*B[n,k] (+bias[n]); batched (bz)
// causalSkip drops blocks with bx > by
// ---------------------------------------------------------------------------
template <typename TA, typename TC>
__global__ __launch_bounds__(256, 2) void gemm_nt_h(
    const TA* __restrict__ A, const TA* __restrict__ B,
    const float* __restrict__ bias, TC* __restrict__ C,
    int M, int N, int K, float alpha,
    long strideA, long strideB, long strideC, int causalSkip)
{
    int bx = blockIdx.x, by = blockIdx.y, bz = blockIdx.z;
    if (causalSkip && bx > by) return;
    A += (size_t)bz * strideA;
    B += (size_t)bz * strideB;
    C += (size_t)bz * strideC;

    __shared__ __half sA[2][BM * SST];
    __shared__ __half sB[2][BN * SST];

    int tid = threadIdx.x;
    int warp = tid >> 5, lane = tid & 31;
    int wr = warp & 3, wc = warp >> 2;   // 4x2 warps; warp tile 32x64
    int qr = lane >> 2, rr = lane & 3;
    int lrow = lane & 15, lkc = (lane >> 4) * 8;  // ldmatrix lane addressing

    int lr = tid >> 1;            // 0..127 staging row
    int lc = (tid & 1) * 16;      // half-col 0 / 16

    const TA* Ap = A + (size_t)(by * BM + lr) * K + lc;
    const TA* Bp = B + (size_t)(bx * BN + lr) * K + lc;

    float acc[2][8][4];
#pragma unroll
    for (int mt = 0; mt < 2; mt++)
#pragma unroll
        for (int nt = 0; nt < 8; nt++)
#pragma unroll
            for (int i = 0; i < 4; i++) acc[mt][nt][i] = 0.f;

    int nIter = K / BK;
    uint4 ua0, ua1, ub0, ub1;

    load16(Ap, ua0, ua1);
    load16(Bp, ub0, ub1);
    *(uint4*)&sA[0][lr * SST + lc] = ua0;
    *(uint4*)&sA[0][lr * SST + lc + 8] = ua1;
    *(uint4*)&sB[0][lr * SST + lc] = ub0;
    *(uint4*)&sB[0][lr * SST + lc + 8] = ub1;
    __syncthreads();

    for (int it = 0; it < nIter; ++it) {
        int buf = it & 1;
        if (it + 1 < nIter) {
            int k0 = (it + 1) * BK;
            load16(Ap + k0, ua0, ua1);
            load16(Bp + k0, ub0, ub1);
        }
        unsigned sa = (unsigned)__cvta_generic_to_shared(&sA[buf][0]);
        unsigned sb = (unsigned)__cvta_generic_to_shared(&sB[buf][0]);
#pragma unroll
        for (int ks = 0; ks < 2; ks++) {
            int kb = ks * 16;
            unsigned af[2][4], bf[8][2];
#pragma unroll
            for (int mt = 0; mt < 2; mt++) {
                int row = wr * 32 + mt * 16 + lrow;
                ldsm4(af[mt][0], af[mt][1], af[mt][2], af[mt][3],
                      sa + (unsigned)(row * SST + kb + lkc) * 2);
            }
#pragma unroll
            for (int ng = 0; ng < 4; ng++) {
                int row = wc * 64 + ng * 16 + lrow;
                unsigned r0, r1, r2, r3;
                ldsm4(r0, r1, r2, r3, sb + (unsigned)(row * SST + kb + lkc) * 2);
                bf[2 * ng][0] = r0; bf[2 * ng][1] = r2;
                bf[2 * ng + 1][0] = r1; bf[2 * ng + 1][1] = r3;
            }
#pragma unroll
            for (int mt = 0; mt < 2; mt++)
#pragma unroll
                for (int nt = 0; nt < 8; nt++)
                    mma16816(acc[mt][nt], af[mt], bf[nt]);
        }
        if (it + 1 < nIter) {
            int nb = buf ^ 1;
            *(uint4*)&sA[nb][lr * SST + lc] = ua0;
            *(uint4*)&sA[nb][lr * SST + lc + 8] = ua1;
            *(uint4*)&sB[nb][lr * SST + lc] = ub0;
            *(uint4*)&sB[nb][lr * SST + lc + 8] = ub1;
        }
        __syncthreads();
    }

    // epilogue
#pragma unroll
    for (int mt = 0; mt < 2; mt++) {
#pragma unroll
        for (int nt = 0; nt < 8; nt++) {
            int row = by * BM + wr * 32 + mt * 16 + qr;
            int col = bx * BN + wc * 64 + nt * 8 + rr * 2;
            float bv0 = bias ? bias[col] : 0.f;
            float bv1 = bias ? bias[col + 1] : 0.f;
            float x0 = acc[mt][nt][0] * alpha + bv0;
            float x1 = acc[mt][nt][1] * alpha + bv1;
            float x2 = acc[mt][nt][2] * alpha + bv0;
            float x3 = acc[mt][nt][3] * alpha + bv1;
            if constexpr (sizeof(TC) == 2) {
                *(unsigned*)&C[(size_t)row * N + col] = packh2(x0, x1);
                *(unsigned*)&C[(size_t)(row + 8) * N + col] = packh2(x2, x3);
            } else {
                float2 v;
                v.x = x0; v.y = x1;
                *(float2*)&C[(size_t)row * N + col] = v;
                v.x = x2; v.y = x3;
                *(float2*)&C[(size_t)(row + 8) * N + col] = v;
            }
        }
    }
}

// ---------------------------------------------------------------------------
// NN gemm: C[m,n] = sum_k A[m,k]*B[k,n]; A fp32 (P), B fp16 (V); batched
// causalK clips k loop at (by+1)*BM
// ---------------------------------------------------------------------------
__global__ __launch_bounds__(256, 2) void gemm_nn_h(
    const float* __restrict__ A, const __half* __restrict__ B,
    float* __restrict__ C,
    int M, int N, int K,
    long strideA, long strideB, long strideC, int causalK)
{
    int bx = blockIdx.x, by = blockIdx.y, bz = blockIdx.z;
    A += (size_t)bz * strideA;
    B += (size_t)bz * strideB;
    C += (size_t)bz * strideC;

    __shared__ __half sA[2][BM * SST];
    __shared__ __half sB[2][BN * SST];

    int tid = threadIdx.x;
    int warp = tid >> 5, lane = tid & 31;
    int wr = warp & 3, wc = warp >> 2;
    int qr = lane >> 2, rr = lane & 3;
    int lrow = lane & 15, lkc = (lane >> 4) * 8;

    int lr = tid >> 1;
    int lc = (tid & 1) * 16;
    int bn = tid & 127;        // V transpose loader: n index
    int kg = tid >> 7;         // k group (0/1) -> k offsets kg*16..kg*16+15

    const float* Ap = A + (size_t)(by * BM + lr) * K + lc;
    const __half* Bp = B + (size_t)(bx * BN + bn);

    int kEnd = causalK ? min(K, (by + 1) * BM) : K;
    int nIter = kEnd / BK;

    float acc[2][8][4];
#pragma unroll
    for (int mt = 0; mt < 2; mt++)
#pragma unroll
        for (int nt = 0; nt < 8; nt++)
#pragma unroll
            for (int i = 0; i < 4; i++) acc[mt][nt][i] = 0.f;

    uint4 ua0, ua1;
    __half hb[16];

    load16(Ap, ua0, ua1);
#pragma unroll
    for (int j = 0; j < 16; j++) hb[j] = Bp[(size_t)(kg * 16 + j) * N];
    {
        *(uint4*)&sA[0][lr * SST + lc] = ua0;
        *(uint4*)&sA[0][lr * SST + lc + 8] = ua1;
        uint4 u;
        u.x = *(unsigned*)&hb[0];  u.y = *(unsigned*)&hb[2];
        u.z = *(unsigned*)&hb[4];  u.w = *(unsigned*)&hb[6];
        *(uint4*)&sB[0][bn * SST + kg * 16] = u;
        u.x = *(unsigned*)&hb[8];  u.y = *(unsigned*)&hb[10];
        u.z = *(unsigned*)&hb[12]; u.w = *(unsigned*)&hb[14];
        *(uint4*)&sB[0][bn * SST + kg * 16 + 8] = u;
    }
    __syncthreads();

    for (int it = 0; it < nIter; ++it) {
        int buf = it & 1;
        if (it + 1 < nIter) {
            int k0 = (it + 1) * BK;
            load16(Ap + k0, ua0, ua1);
#pragma unroll
            for (int j = 0; j < 16; j++) hb[j] = Bp[(size_t)(k0 + kg * 16 + j) * N];
        }
        unsigned sa = (unsigned)__cvta_generic_to_shared(&sA[buf][0]);
        unsigned sb = (unsigned)__cvta_generic_to_shared(&sB[buf][0]);
#pragma unroll
        for (int ks = 0; ks < 2; ks++) {
            int kb = ks * 16;
            unsigned af[2][4], bf[8][2];
#pragma unroll
            for (int mt = 0; mt < 2; mt++) {
                int row = wr * 32 + mt * 16 + lrow;
                ldsm4(af[mt][0], af[mt][1], af[mt][2], af[mt][3],
                      sa + (unsigned)(row * SST + kb + lkc) * 2);
            }
#pragma unroll
            for (int ng = 0; ng < 4; ng++) {
                int row = wc * 64 + ng * 16 + lrow;
                unsigned r0, r1, r2, r3;
                ldsm4(r0, r1, r2, r3, sb + (unsigned)(row * SST + kb + lkc) * 2);
                bf[2 * ng][0] = r0; bf[2 * ng][1] = r2;
                bf[2 * ng + 1][0] = r1; bf[2 * ng + 1][1] = r3;
            }
#pragma unroll
            for (int mt = 0; mt < 2; mt++)
#pragma unroll
                for (int nt = 0; nt < 8; nt++)
                    mma16816(acc[mt][nt], af[mt], bf[nt]);
        }
        if (it + 1 < nIter) {
            int nb = buf ^ 1;
            *(uint4*)&sA[nb][lr * SST + lc] = ua0;
            *(uint4*)&sA[nb][lr * SST + lc + 8] = ua1;
            uint4 u;
            u.x = *(unsigned*)&hb[0];  u.y = *(unsigned*)&hb[2];
            u.z = *(unsigned*)&hb[4];  u.w = *(unsigned*)&hb[6];
            *(uint4*)&sB[nb][bn * SST + kg * 16] = u;
            u.x = *(unsigned*)&hb[8];  u.y = *(unsigned*)&hb[10];
            u.z = *(unsigned*)&hb[12]; u.w = *(unsigned*)&hb[14];
            *(uint4*)&sB[nb][bn * SST + kg * 16 + 8] = u;
        }
        __syncthreads();
    }

#pragma unroll
    for (int mt = 0; mt < 2; mt++) {
#pragma unroll
        for (int nt = 0; nt < 8; nt++) {
            int row = by * BM + wr * 32 + mt * 16 + qr;
            int col = bx * BN + wc * 64 + nt * 8 + rr * 2;
            float2 v;
            v.x = acc[mt][nt][0]; v.y = acc[mt][nt][1];
            *(float2*)&C[(size_t)row * N + col] = v;
            v.x = acc[mt][nt][2]; v.y = acc[mt][nt][3];
            *(float2*)&C[(size_t)(row + 8) * N + col] = v;
        }
    }
}

// ---------------------------------------------------------------------------
// Causal row softmax in place on S[b,q,0..q]; zeros the tail [q+1, T)
// ---------------------------------------------------------------------------
__global__ void softmax_causal(float* __restrict__ S)
{
    int q = blockIdx.x, b = blockIdx.y;
    float* row = S + ((size_t)b * TDIM + q) * TDIM;
    int len = q + 1;
    int tid = threadIdx.x;
    int lane = tid & 31, warp = tid >> 5;

    __shared__ float smax[8];
    __shared__ float ssum[8];

    float m = -1e30f;
    for (int i = tid; i < len; i += 256) m = fmaxf(m, row[i]);
#pragma unroll
    for (int o = 16; o; o >>= 1) m = fmaxf(m, __shfl_xor_sync(0xffffffffu, m, o));
    if (lane == 0) smax[warp] = m;
    __syncthreads();
    if (tid == 0) {
        float v = smax[0];
#pragma unroll
        for (int i = 1; i < 8; i++) v = fmaxf(v, smax[i]);
        smax[0] = v;
    }
    __syncthreads();
    m = smax[0];

    float sum = 0.f;
    for (int i = tid; i < len; i += 256) {
        float e = __expf(row[i] - m);
        row[i] = e;
        sum += e;
    }
#pragma unroll
    for (int o = 16; o; o >>= 1) sum += __shfl_xor_sync(0xffffffffu, sum, o);
    if (lane == 0) ssum[warp] = sum;
    __syncthreads();
    if (tid == 0) {
        float v = 0.f;
#pragma unroll
        for (int i = 0; i < 8; i++) v += ssum[i];
        ssum[0] = v;
    }
    __syncthreads();
    float inv = 1.f / ssum[0];

    for (int i = tid; i < len; i += 256) row[i] *= inv;
    for (int i = len + tid; i < TDIM; i += 256) row[i] = 0.f;
}

extern "C" void kernel_launch(void* const* d_in, const int* in_sizes, int n_in,
                              void* d_out, int out_size)
{
    const float* qx = (const float*)d_in[0];
    const float* kx = (const float*)d_in[1];
    const float* vx = (const float*)d_in[2];
    const float* Wq = (const float*)d_in[3];
    const float* bq = (const float*)d_in[4];
    const float* Wk = (const float*)d_in[5];
    const float* bk = (const float*)d_in[6];
    const float* Wv = (const float*)d_in[7];
    const float* bv = (const float*)d_in[8];
    float* out = (float*)d_out;

    __half *pQ, *pK, *pV;
    float* pS;
    cudaGetSymbolAddress((void**)&pQ, g_Q);
    cudaGetSymbolAddress((void**)&pK, g_K);
    cudaGetSymbolAddress((void**)&pV, g_V);
    cudaGetSymbolAddress((void**)&pS, g_S);

    dim3 blk(256);

    // Projections: X(16384x1024) @ W^T + b  -> fp16 Q/K/V scratch
    dim3 gproj(DEMB / BN, (NB * TDIM) / BM, 1);
    gemm_nt_h<float, __half><<<gproj, blk>>>(qx, Wq, bq, pQ, NB * TDIM, DEMB, DEMB,
                                             1.f, 0, 0, 0, 0);
    gemm_nt_h<float, __half><<<gproj, blk>>>(kx, Wk, bk, pK, NB * TDIM, DEMB, DEMB,
                                             1.f, 0, 0, 0, 0);
    gemm_nt_h<float, __half><<<gproj, blk>>>(vx, Wv, bv, pV, NB * TDIM, DEMB, DEMB,
                                             1.f, 0, 0, 0, 0);

    // S = Q K^T / 32 (fp16 in, fp32 out), upper-triangle blocks skipped
    dim3 gattn(TDIM / BN, TDIM / BM, NB);
    gemm_nt_h<__half, float><<<gattn, blk>>>(pQ, pK, nullptr, pS, TDIM, TDIM, DEMB,
                                             0.03125f,
                                             (long)TDIM * DEMB, (long)TDIM * DEMB,
                                             (long)TDIM * TDIM, 1);

    // causal softmax in place (writes exact zeros above diagonal)
    softmax_causal<<<dim3(TDIM, NB), 256>>>(pS);

    // O = P V, k-loop clipped at the diagonal
    gemm_nn_h<<<gattn, blk>>>(pS, pV, out, TDIM, DEMB, TDIM,
                              (long)TDIM * TDIM, (long)TDIM * DEMB,
                              (long)TDIM * DEMB, 1);
}

// round 5
// speedup vs baseline: 5.7603x; 1.3816x over previous
#include <cuda_runtime.h>
#include <cuda_fp16.h>
#include <stdint.h>

#define NB 16
#define TDIM 1024
#define DEMB 1024

// ---------------- scratch (__device__ globals, allocation-free rule) --------
__device__ __half g_Q[(size_t)NB * TDIM * DEMB];
__device__ __half g_K[(size_t)NB * TDIM * DEMB];
__device__ __half g_V[(size_t)NB * TDIM * DEMB];
__device__ __half g_P[(size_t)NB * TDIM * TDIM];
__device__ float  g_S[(size_t)NB * TDIM * TDIM];
__device__ __half g_Xq[(size_t)NB * TDIM * DEMB];
__device__ __half g_Xk[(size_t)NB * TDIM * DEMB];
__device__ __half g_Xv[(size_t)NB * TDIM * DEMB];
__device__ __half g_Wqh[DEMB * DEMB];
__device__ __half g_Wkh[DEMB * DEMB];
__device__ __half g_Wvh[DEMB * DEMB];

// ---------------- smem: 3-stage A + 3-stage B, 16KB stages ------------------
constexpr int STG = 16384;            // 128 rows x 128B
constexpr int SB_OFF = 3 * STG;       // B stages start
constexpr int SMEM_BYTES = 6 * STG + 1024;

#define CP_CG(dst, src) \
    asm volatile("cp.async.cg.shared.global [%0], [%1], 16;" :: "r"(dst), "l"(src))
#define CP_COMMIT() asm volatile("cp.async.commit_group;" ::: "memory")
#define CP_WAIT(n)  asm volatile("cp.async.wait_group %0;" :: "n"(n) : "memory")

__device__ __forceinline__ unsigned packh2(float x, float y) {
    __half2 h = __floats2half2_rn(x, y);
    return *(unsigned*)&h;
}

__device__ __forceinline__ void ldsm4(unsigned& r0, unsigned& r1, unsigned& r2, unsigned& r3,
                                      unsigned a) {
    asm volatile("ldmatrix.sync.aligned.m8n8.x4.shared.b16 {%0,%1,%2,%3}, [%4];"
                 : "=r"(r0), "=r"(r1), "=r"(r2), "=r"(r3) : "r"(a));
}
__device__ __forceinline__ void ldsm4t(unsigned& r0, unsigned& r1, unsigned& r2, unsigned& r3,
                                       unsigned a) {
    asm volatile("ldmatrix.sync.aligned.m8n8.x4.trans.shared.b16 {%0,%1,%2,%3}, [%4];"
                 : "=r"(r0), "=r"(r1), "=r"(r2), "=r"(r3) : "r"(a));
}
__device__ __forceinline__ void mma16816(float* c, const unsigned* a, const unsigned* b) {
    asm volatile(
        "mma.sync.aligned.m16n8k16.row.col.f32.f16.f16.f32 "
        "{%0,%1,%2,%3},{%4,%5,%6,%7},{%8,%9},{%0,%1,%2,%3};"
        : "+f"(c[0]), "+f"(c[1]), "+f"(c[2]), "+f"(c[3])
        : "r"(a[0]), "r"(a[1]), "r"(a[2]), "r"(a[3]), "r"(b[0]), "r"(b[1]));
}

// stage 128 rows x 64 halves (k-major, 128B rows), SW128 swizzle
// thread t: row r=t>>1, 4 chunks starting at (t&1)*4
__device__ __forceinline__ void cp_km(unsigned dst, const char* src, size_t rowBytes,
                                      int r, int cg) {
    const char* p = src + (size_t)r * rowBytes + cg * 16;
    unsigned d = dst + r * 128;
#pragma unroll
    for (int j = 0; j < 4; j++) {
        unsigned c = cg + j;
        CP_CG(d + ((c ^ (r & 7)) << 4), p + j * 16);
    }
}

// stage V chunk: 64 k-rows x 128 n-halves (256B rows), swizzle on 16 chunks
// thread t: k=t>>2, 4 chunks from (t&3)*4
__device__ __forceinline__ void cp_vrow(unsigned dst, const char* src, size_t rowBytes,
                                        int k, int cg) {
    const char* p = src + (size_t)k * rowBytes + cg * 16;
    unsigned d = dst + k * 256;
#pragma unroll
    for (int j = 0; j < 4; j++) {
        unsigned c = cg + j;
        CP_CG(d + ((c ^ (k & 7)) << 4), p + j * 16);
    }
}

// ============================================================================
// NT gemm: C[m,n] = alpha*sum_k A[m,k]*B[n,k] (+bias); A,B half k-major.
// TC = __half or float. CAUSAL skips bx>by blocks. batched via bz strides.
// ============================================================================
template <typename TC, bool CAUSAL>
__global__ __launch_bounds__(256, 2) void hgemm_nt(
    const __half* __restrict__ A, const __half* __restrict__ B,
    const float* __restrict__ bias, TC* __restrict__ C,
    int N, int K, float alpha, long strideA, long strideB, long strideC)
{
    int bx = blockIdx.x, by = blockIdx.y, bz = blockIdx.z;
    if (CAUSAL && bx > by) return;

    extern __shared__ char raw[];
    char* smem = (char*)(((uintptr_t)raw + 1023) & ~(uintptr_t)1023);
    unsigned sbase = (unsigned)__cvta_generic_to_shared(smem);

    int tid = threadIdx.x, warp = tid >> 5, lane = tid & 31;
    int wr = warp & 3, wc = warp >> 2;       // 4x2 warps, warp tile 32x64
    int qr = lane >> 2, rr = lane & 3;
    int r = tid >> 1, cg = (tid & 1) * 4;    // staging role

    const char* pa = (const char*)(A + (size_t)bz * strideA + (size_t)(by * 128) * K);
    const char* pb = (const char*)(B + (size_t)bz * strideB + (size_t)(bx * 128) * K);
    C += (size_t)bz * strideC;
    size_t rowB = (size_t)K * 2;

    float acc[2][8][4];
#pragma unroll
    for (int mt = 0; mt < 2; mt++)
#pragma unroll
        for (int nt = 0; nt < 8; nt++)
#pragma unroll
            for (int i = 0; i < 4; i++) acc[mt][nt][i] = 0.f;

    const int nIter = K / 64;

    // prologue: stages 0,1
    cp_km(sbase, pa, rowB, r, cg);
    cp_km(sbase + SB_OFF, pb, rowB, r, cg);
    CP_COMMIT();
    cp_km(sbase + STG, pa + 128, rowB, r, cg);
    cp_km(sbase + SB_OFF + STG, pb + 128, rowB, r, cg);
    CP_COMMIT();

    for (int it = 0; it < nIter; ++it) {
        if (it + 2 < nIter) {
            int s = (it + 2) % 3;
            cp_km(sbase + s * STG, pa + (size_t)(it + 2) * 128, rowB, r, cg);
            cp_km(sbase + SB_OFF + s * STG, pb + (size_t)(it + 2) * 128, rowB, r, cg);
            CP_COMMIT();
            CP_WAIT(2);
        } else if (it + 1 < nIter) {
            CP_WAIT(1);
        } else {
            CP_WAIT(0);
        }
        __syncthreads();

        unsigned sa = sbase + (it % 3) * STG;
        unsigned sb = sbase + SB_OFF + (it % 3) * STG;
#pragma unroll
        for (int ks = 0; ks < 4; ks++) {
            int kc = ks * 2;
            unsigned af[2][4], bf[8][2];
#pragma unroll
            for (int mt = 0; mt < 2; mt++) {
                int row = wr * 32 + mt * 16 + (lane & 15);
                int ch = kc + (lane >> 4);
                ldsm4(af[mt][0], af[mt][1], af[mt][2], af[mt][3],
                      sa + row * 128 + ((ch ^ (row & 7)) << 4));
            }
#pragma unroll
            for (int ng = 0; ng < 4; ng++) {
                int row = wc * 64 + ng * 16 + (lane & 15);
                int ch = kc + (lane >> 4);
                unsigned r0, r1, r2, r3;
                ldsm4(r0, r1, r2, r3, sb + row * 128 + ((ch ^ (row & 7)) << 4));
                bf[2 * ng][0] = r0; bf[2 * ng][1] = r2;
                bf[2 * ng + 1][0] = r1; bf[2 * ng + 1][1] = r3;
            }
#pragma unroll
            for (int mt = 0; mt < 2; mt++)
#pragma unroll
                for (int nt = 0; nt < 8; nt++)
                    mma16816(acc[mt][nt], af[mt], bf[nt]);
        }
        __syncthreads();
    }

    // epilogue
#pragma unroll
    for (int mt = 0; mt < 2; mt++) {
#pragma unroll
        for (int nt = 0; nt < 8; nt++) {
            int row = by * 128 + wr * 32 + mt * 16 + qr;
            int col = bx * 128 + wc * 64 + nt * 8 + rr * 2;
            float b0 = bias ? bias[col] : 0.f;
            float b1 = bias ? bias[col + 1] : 0.f;
            float x0 = acc[mt][nt][0] * alpha + b0;
            float x1 = acc[mt][nt][1] * alpha + b1;
            float x2 = acc[mt][nt][2] * alpha + b0;
            float x3 = acc[mt][nt][3] * alpha + b1;
            if constexpr (sizeof(TC) == 2) {
                *(unsigned*)&C[(size_t)row * N + col] = packh2(x0, x1);
                *(unsigned*)&C[(size_t)(row + 8) * N + col] = packh2(x2, x3);
            } else {
                float2 v;
                v.x = x0; v.y = x1;
                *(float2*)&C[(size_t)row * N + col] = v;
                v.x = x2; v.y = x3;
                *(float2*)&C[(size_t)(row + 8) * N + col] = v;
            }
        }
    }
}

// ============================================================================
// PV: O[m,n] = sum_k P[m,k]*V[k,n]; P half k-major, V half row-major [k][n],
// B fragments via ldmatrix.trans. k clipped at diagonal. batched.
// ============================================================================
__global__ __launch_bounds__(256, 2) void hgemm_pv(
    const __half* __restrict__ P, const __half* __restrict__ V,
    float* __restrict__ O)
{
    int bx = blockIdx.x, by = blockIdx.y, bz = blockIdx.z;

    extern __shared__ char raw[];
    char* smem = (char*)(((uintptr_t)raw + 1023) & ~(uintptr_t)1023);
    unsigned sbase = (unsigned)__cvta_generic_to_shared(smem);

    int tid = threadIdx.x, warp = tid >> 5, lane = tid & 31;
    int wr = warp & 3, wc = warp >> 2;
    int qr = lane >> 2, rr = lane & 3;
    int r = tid >> 1, cg = (tid & 1) * 4;       // P staging
    int vk = tid >> 2, vg = (tid & 3) * 4;      // V staging

    const char* pa = (const char*)(P + (size_t)bz * TDIM * TDIM + (size_t)(by * 128) * TDIM);
    const char* pv = (const char*)(V + (size_t)bz * TDIM * DEMB + bx * 128);
    float* C = O + (size_t)bz * TDIM * DEMB;
    size_t rowA = (size_t)TDIM * 2;
    size_t rowV = (size_t)DEMB * 2;

    float acc[2][8][4];
#pragma unroll
    for (int mt = 0; mt < 2; mt++)
#pragma unroll
        for (int nt = 0; nt < 8; nt++)
#pragma unroll
            for (int i = 0; i < 4; i++) acc[mt][nt][i] = 0.f;

    const int nIter = (by + 1) * 2;   // k up to (by+1)*128, BK=64

    cp_km(sbase, pa, rowA, r, cg);
    cp_vrow(sbase + SB_OFF, pv, rowV, vk, vg);
    CP_COMMIT();
    cp_km(sbase + STG, pa + 128, rowA, r, cg);
    cp_vrow(sbase + SB_OFF + STG, pv + 64 * rowV, rowV, vk, vg);
    CP_COMMIT();

    for (int it = 0; it < nIter; ++it) {
        if (it + 2 < nIter) {
            int s = (it + 2) % 3;
            cp_km(sbase + s * STG, pa + (size_t)(it + 2) * 128, rowA, r, cg);
            cp_vrow(sbase + SB_OFF + s * STG, pv + (size_t)(it + 2) * 64 * rowV, rowV, vk, vg);
            CP_COMMIT();
            CP_WAIT(2);
        } else if (it + 1 < nIter) {
            CP_WAIT(1);
        } else {
            CP_WAIT(0);
        }
        __syncthreads();

        unsigned sa = sbase + (it % 3) * STG;
        unsigned sb = sbase + SB_OFF + (it % 3) * STG;
#pragma unroll
        for (int ks = 0; ks < 4; ks++) {
            int kc = ks * 2;
            unsigned af[2][4], bf[8][2];
#pragma unroll
            for (int mt = 0; mt < 2; mt++) {
                int row = wr * 32 + mt * 16 + (lane & 15);
                int ch = kc + (lane >> 4);
                ldsm4(af[mt][0], af[mt][1], af[mt][2], af[mt][3],
                      sa + row * 128 + ((ch ^ (row & 7)) << 4));
            }
#pragma unroll
            for (int ng = 0; ng < 4; ng++) {
                int krow = ks * 16 + (lane & 15);
                int cb = (wc * 64 + ng * 16) >> 3;
                int ch = cb + (lane >> 4);
                unsigned r0, r1, r2, r3;
                ldsm4t(r0, r1, r2, r3, sb + krow * 256 + ((ch ^ (krow & 7)) << 4));
                bf[2 * ng][0] = r0; bf[2 * ng][1] = r1;
                bf[2 * ng + 1][0] = r2; bf[2 * ng + 1][1] = r3;
            }
#pragma unroll
            for (int mt = 0; mt < 2; mt++)
#pragma unroll
                for (int nt = 0; nt < 8; nt++)
                    mma16816(acc[mt][nt], af[mt], bf[nt]);
        }
        __syncthreads();
    }

#pragma unroll
    for (int mt = 0; mt < 2; mt++) {
#pragma unroll
        for (int nt = 0; nt < 8; nt++) {
            int row = by * 128 + wr * 32 + mt * 16 + qr;
            int col = bx * 128 + wc * 64 + nt * 8 + rr * 2;
            float2 v;
            v.x = acc[mt][nt][0]; v.y = acc[mt][nt][1];
            *(float2*)&C[(size_t)row * DEMB + col] = v;
            v.x = acc[mt][nt][2]; v.y = acc[mt][nt][3];
            *(float2*)&C[(size_t)(row + 8) * DEMB + col] = v;
        }
    }
}

// ---------------------------------------------------------------------------
// f32 -> f16 convert (grid-stride over float4)
// ---------------------------------------------------------------------------
__global__ void f2h(const float* __restrict__ x, __half* __restrict__ y, int n4)
{
    for (int i = blockIdx.x * blockDim.x + threadIdx.x; i < n4;
         i += gridDim.x * blockDim.x) {
        float4 v = *(const float4*)(x + (size_t)i * 4);
        uint2 u;
        u.x = packh2(v.x, v.y);
        u.y = packh2(v.z, v.w);
        *(uint2*)(y + (size_t)i * 4) = u;
    }
}

// ---------------------------------------------------------------------------
// Causal softmax: reads f32 S row, writes half P row; zeros tail [q+1, T)
// ---------------------------------------------------------------------------
__global__ void softmax_causal(const float* __restrict__ S, __half* __restrict__ P)
{
    int q = blockIdx.x, b = blockIdx.y;
    const float* row = S + ((size_t)b * TDIM + q) * TDIM;
    __half* prow = P + ((size_t)b * TDIM + q) * TDIM;
    int len = q + 1;
    int tid = threadIdx.x;
    int lane = tid & 31, warp = tid >> 5;

    __shared__ float smax[8];
    __shared__ float ssum[8];

    float m = -1e30f;
    for (int i = tid; i < len; i += 256) m = fmaxf(m, row[i]);
#pragma unroll
    for (int o = 16; o; o >>= 1) m = fmaxf(m, __shfl_xor_sync(0xffffffffu, m, o));
    if (lane == 0) smax[warp] = m;
    __syncthreads();
    if (tid == 0) {
        float v = smax[0];
#pragma unroll
        for (int i = 1; i < 8; i++) v = fmaxf(v, smax[i]);
        smax[0] = v;
    }
    __syncthreads();
    m = smax[0];

    float sum = 0.f;
    for (int i = tid; i < len; i += 256) sum += __expf(row[i] - m);
#pragma unroll
    for (int o = 16; o; o >>= 1) sum += __shfl_xor_sync(0xffffffffu, sum, o);
    if (lane == 0) ssum[warp] = sum;
    __syncthreads();
    if (tid == 0) {
        float v = 0.f;
#pragma unroll
        for (int i = 0; i < 8; i++) v += ssum[i];
        ssum[0] = v;
    }
    __syncthreads();
    float inv = 1.f / ssum[0];

    for (int i = tid; i < len; i += 256)
        prow[i] = __float2half(__expf(row[i] - m) * inv);
    for (int i = len + tid; i < TDIM; i += 256)
        prow[i] = __float2half(0.f);
}

extern "C" void kernel_launch(void* const* d_in, const int* in_sizes, int n_in,
                              void* d_out, int out_size)
{
    const float* qx = (const float*)d_in[0];
    const float* kx = (const float*)d_in[1];
    const float* vx = (const float*)d_in[2];
    const float* Wq = (const float*)d_in[3];
    const float* bq = (const float*)d_in[4];
    const float* Wk = (const float*)d_in[5];
    const float* bk = (const float*)d_in[6];
    const float* Wv = (const float*)d_in[7];
    const float* bv = (const float*)d_in[8];
    float* out = (float*)d_out;

    __half *pQ, *pK, *pV, *pP, *pXq, *pXk, *pXv, *pWq, *pWk, *pWv;
    float* pS;
    cudaGetSymbolAddress((void**)&pQ, g_Q);
    cudaGetSymbolAddress((void**)&pK, g_K);
    cudaGetSymbolAddress((void**)&pV, g_V);
    cudaGetSymbolAddress((void**)&pP, g_P);
    cudaGetSymbolAddress((void**)&pS, g_S);
    cudaGetSymbolAddress((void**)&pXq, g_Xq);
    cudaGetSymbolAddress((void**)&pXk, g_Xk);
    cudaGetSymbolAddress((void**)&pXv, g_Xv);
    cudaGetSymbolAddress((void**)&pWq, g_Wqh);
    cudaGetSymbolAddress((void**)&pWk, g_Wkh);
    cudaGetSymbolAddress((void**)&pWv, g_Wvh);

    cudaFuncSetAttribute(hgemm_nt<__half, false>,
                         cudaFuncAttributeMaxDynamicSharedMemorySize, SMEM_BYTES);
    cudaFuncSetAttribute(hgemm_nt<float, true>,
                         cudaFuncAttributeMaxDynamicSharedMemorySize, SMEM_BYTES);
    cudaFuncSetAttribute(hgemm_pv,
                         cudaFuncAttributeMaxDynamicSharedMemorySize, SMEM_BYTES);

    const int NX4 = NB * TDIM * DEMB / 4;   // 4M float4
    const int NW4 = DEMB * DEMB / 4;
    f2h<<<2048, 256>>>(qx, pXq, NX4);
    f2h<<<2048, 256>>>(kx, pXk, NX4);
    f2h<<<2048, 256>>>(vx, pXv, NX4);
    f2h<<<512, 256>>>(Wq, pWq, NW4);
    f2h<<<512, 256>>>(Wk, pWk, NW4);
    f2h<<<512, 256>>>(Wv, pWv, NW4);

    dim3 blk(256);

    // Projections -> half Q/K/V
    dim3 gproj(DEMB / 128, (NB * TDIM) / 128, 1);
    hgemm_nt<__half, false><<<gproj, blk, SMEM_BYTES>>>(
        pXq, pWq, bq, pQ, DEMB, DEMB, 1.f, 0, 0, 0);
    hgemm_nt<__half, false><<<gproj, blk, SMEM_BYTES>>>(
        pXk, pWk, bk, pK, DEMB, DEMB, 1.f, 0, 0, 0);
    hgemm_nt<__half, false><<<gproj, blk, SMEM_BYTES>>>(
        pXv, pWv, bv, pV, DEMB, DEMB, 1.f, 0, 0, 0);

    // S = Q K^T / 32 (causal blocks only)
    dim3 gattn(TDIM / 128, TDIM / 128, NB);
    hgemm_nt<float, true><<<gattn, blk, SMEM_BYTES>>>(
        pQ, pK, nullptr, pS, TDIM, DEMB, 0.03125f,
        (long)TDIM * DEMB, (long)TDIM * DEMB, (long)TDIM * TDIM);

    // softmax: S (f32) -> P (half), zero tail
    softmax_causal<<<dim3(TDIM, NB), 256>>>(pS, pP);

    // O = P V (k clipped at diagonal)
    hgemm_pv<<<gattn, blk, SMEM_BYTES>>>(pP, pV, out);
}